// round 1
// baseline (speedup 1.0000x reference)
#include <cuda_runtime.h>
#include <math.h>

#define C     64
#define A     128
#define HID   256
#define NA    4
#define HW    512
#define NPOS  (HW * HW)          // 262144 positions
#define TM    128                // positions per tile
#define NTILES (NPOS / TM)       // 2048
#define LDP   132                // padded SMEM row (128 + 4)
#define GRID_A 148
#define GRID_G 16
#define NTHREADS 256

// Per-CTA online-softmax partials + LSTM gate scratch (no allocs allowed).
__device__ float g_m[GRID_A];
__device__ float g_l[GRID_A];
__device__ float g_acc[GRID_A * A];
__device__ float g_gates[4 * HID];

#define SMEM_FLOATS (2 * C * LDP + 2 * A * LDP + 6 * A + 8 + 4)

// ---------------------------------------------------------------------------
// Kernel A: fused conv(1x1)+relu -> att1 -> scores -> online softmax + acc
// Persistent grid; each CTA owns a subset of the 2048 position tiles.
// ---------------------------------------------------------------------------
__global__ void __launch_bounds__(NTHREADS, 1)
attn_kernel(const float* __restrict__ img,
            const float* __restrict__ conv_w, const float* __restrict__ conv_b,
            const float* __restrict__ ia_w,   const float* __restrict__ ia_b,
            const float* __restrict__ fa_w)
{
    extern __shared__ float sm[];
    float* s_w1   = sm;                    // [C][LDP]  w1[c][a] = conv_w[a][c]
    float* s_img  = s_w1  + C * LDP;       // [C][LDP]  img[c][p]
    float* s_w2   = s_img + C * LDP;       // [A][LDP]  w2[a][j] = ia_w[j][a]
    float* s_feat = s_w2  + A * LDP;       // [A][LDP]  feat[a][p]
    float* s_cb    = s_feat + A * LDP;     // conv_b   [A]
    float* s_ib    = s_cb + A;             // ia_b     [A]
    float* s_fw    = s_ib + A;             // fa_w     [A]
    float* s_score = s_fw + A;             // [TM]
    float* s_wexp  = s_score + TM;         // [TM]
    float* s_acc   = s_wexp + TM;          // [A]
    float* s_red   = s_acc + A;            // [8]
    float* s_misc  = s_red + 8;            // [0]=m_run [1]=l_run [2]=new_m [3]=scale

    const int tid  = threadIdx.x;
    const int tx   = tid & 15;             // position-block index (M)
    const int ty   = tid >> 4;             // feature-block index (N)
    const int lane = tid & 31;
    const int wid  = tid >> 5;

    // one-time weight staging (transposed to k-major)
    for (int i = tid; i < A * C; i += NTHREADS) {
        int a = i / C, c = i - a * C;
        s_w1[c * LDP + a] = conv_w[i];
    }
    for (int i = tid; i < A * A; i += NTHREADS) {
        int j = i >> 7, a = i & 127;
        s_w2[a * LDP + j] = ia_w[i];
    }
    if (tid < A) {
        s_cb[tid] = conv_b[tid];
        s_ib[tid] = ia_b[tid];
        s_fw[tid] = fa_w[tid];
        s_acc[tid] = 0.f;
    }
    if (tid == 0) { s_misc[0] = -INFINITY; s_misc[1] = 0.f; }
    __syncthreads();

    for (int t = blockIdx.x; t < NTILES; t += GRID_A) {
        // ---- stage img tile: 64 channels x 128 contiguous positions ----
        const float* src = img + (size_t)t * TM;
        #pragma unroll
        for (int i = 0; i < (C * TM / 4) / NTHREADS; ++i) {   // 8 float4 / thread
            int idx = tid + i * NTHREADS;
            int c = idx >> 5, p4 = idx & 31;
            float4 v = *reinterpret_cast<const float4*>(src + (size_t)c * NPOS + p4 * 4);
            *reinterpret_cast<float4*>(&s_img[c * LDP + p4 * 4]) = v;
        }
        if (tid < TM) s_score[tid] = 0.f;
        __syncthreads();

        // ---- GEMM1: feat[p][a] = sum_c img[c][p] * w1[c][a] ----
        float acc1[8][8];
        #pragma unroll
        for (int i = 0; i < 8; ++i)
            #pragma unroll
            for (int j = 0; j < 8; ++j) acc1[i][j] = 0.f;

        #pragma unroll 4
        for (int k = 0; k < C; ++k) {
            float4 pA = *reinterpret_cast<const float4*>(&s_img[k * LDP + tx * 8]);
            float4 pB = *reinterpret_cast<const float4*>(&s_img[k * LDP + tx * 8 + 4]);
            float4 aA = *reinterpret_cast<const float4*>(&s_w1[k * LDP + ty * 8]);
            float4 aB = *reinterpret_cast<const float4*>(&s_w1[k * LDP + ty * 8 + 4]);
            float pf[8] = {pA.x, pA.y, pA.z, pA.w, pB.x, pB.y, pB.z, pB.w};
            float af[8] = {aA.x, aA.y, aA.z, aA.w, aB.x, aB.y, aB.z, aB.w};
            #pragma unroll
            for (int i = 0; i < 8; ++i)
                #pragma unroll
                for (int j = 0; j < 8; ++j)
                    acc1[i][j] = fmaf(pf[i], af[j], acc1[i][j]);
        }

        // relu + bias, write k-major for GEMM2
        #pragma unroll
        for (int j = 0; j < 8; ++j) {
            float b = s_cb[ty * 8 + j];
            #pragma unroll
            for (int i = 0; i < 8; ++i)
                s_feat[(ty * 8 + j) * LDP + tx * 8 + i] = fmaxf(acc1[i][j] + b, 0.f);
        }
        __syncthreads();

        // ---- GEMM2: att1[p][j] = sum_a feat[a][p] * w2[a][j] ----
        float acc2[8][8];
        #pragma unroll
        for (int i = 0; i < 8; ++i)
            #pragma unroll
            for (int j = 0; j < 8; ++j) acc2[i][j] = 0.f;

        #pragma unroll 4
        for (int k = 0; k < A; ++k) {
            float4 pA = *reinterpret_cast<const float4*>(&s_feat[k * LDP + tx * 8]);
            float4 pB = *reinterpret_cast<const float4*>(&s_feat[k * LDP + tx * 8 + 4]);
            float4 aA = *reinterpret_cast<const float4*>(&s_w2[k * LDP + ty * 8]);
            float4 aB = *reinterpret_cast<const float4*>(&s_w2[k * LDP + ty * 8 + 4]);
            float pf[8] = {pA.x, pA.y, pA.z, pA.w, pB.x, pB.y, pB.z, pB.w};
            float af[8] = {aA.x, aA.y, aA.z, aA.w, aB.x, aB.y, aB.z, aB.w};
            #pragma unroll
            for (int i = 0; i < 8; ++i)
                #pragma unroll
                for (int j = 0; j < 8; ++j)
                    acc2[i][j] = fmaf(pf[i], af[j], acc2[i][j]);
        }

        // scores: s[p] = sum_j relu(att1[p][j] + ia_b[j]) * fa_w[j]
        // (att2 / fa_b are softmax-invariant constants -> dropped)
        {
            float part[8];
            #pragma unroll
            for (int i = 0; i < 8; ++i) part[i] = 0.f;
            #pragma unroll
            for (int j = 0; j < 8; ++j) {
                int jg = ty * 8 + j;
                float bj = s_ib[jg], fj = s_fw[jg];
                #pragma unroll
                for (int i = 0; i < 8; ++i)
                    part[i] += fmaxf(acc2[i][j] + bj, 0.f) * fj;
            }
            #pragma unroll
            for (int i = 0; i < 8; ++i)
                atomicAdd(&s_score[tx * 8 + i], part[i]);
        }
        __syncthreads();

        // ---- tile max ----
        if (tid < TM) {
            float v = s_score[tid];
            #pragma unroll
            for (int off = 16; off; off >>= 1)
                v = fmaxf(v, __shfl_xor_sync(0xffffffffu, v, off));
            if (lane == 0) s_red[wid] = v;
        }
        __syncthreads();
        if (tid == 0) {
            float mt = fmaxf(fmaxf(s_red[0], s_red[1]), fmaxf(s_red[2], s_red[3]));
            float m_old = s_misc[0];
            float nm = fmaxf(m_old, mt);
            s_misc[2] = nm;
            s_misc[3] = (m_old == -INFINITY) ? 0.f : expf(m_old - nm);
        }
        __syncthreads();

        const float nm    = s_misc[2];
        const float scale = s_misc[3];

        // ---- exp weights + tile sum ----
        if (tid < TM) {
            float w = expf(s_score[tid] - nm);
            s_wexp[tid] = w;
            #pragma unroll
            for (int off = 16; off; off >>= 1)
                w += __shfl_xor_sync(0xffffffffu, w, off);
            if (lane == 0) s_red[wid] = w;
        }
        __syncthreads();
        if (tid == 0) {
            float lt = s_red[0] + s_red[1] + s_red[2] + s_red[3];
            s_misc[1] = s_misc[1] * scale + lt;
            s_misc[0] = nm;
        }

        // ---- weighted feature accumulation ----
        if (tid < A) {
            float accv = s_acc[tid] * scale;
            const float* fr = &s_feat[tid * LDP];
            #pragma unroll 4
            for (int p = 0; p < TM; ++p)
                accv = fmaf(s_wexp[p], fr[p], accv);
            s_acc[tid] = accv;
        }
        __syncthreads();
    }

    if (tid < A) g_acc[blockIdx.x * A + tid] = s_acc[tid];
    if (tid == 0) { g_m[blockIdx.x] = s_misc[0]; g_l[blockIdx.x] = s_misc[1]; }
}

// ---------------------------------------------------------------------------
// Kernel B1: LSTM gate pre-activations, spread over 16 CTAs (2 MB weight read)
// ---------------------------------------------------------------------------
__global__ void __launch_bounds__(256)
gates_kernel(const float* __restrict__ action, const float* __restrict__ h0,
             const float* __restrict__ ae_w,  const float* __restrict__ ae_b,
             const float* __restrict__ w_ih,  const float* __restrict__ w_hh,
             const float* __restrict__ b_ih,  const float* __restrict__ b_hh)
{
    __shared__ float s_x[HID];
    __shared__ float s_h[HID];
    const int tid = threadIdx.x, lane = tid & 31, wid = tid >> 5;

    if (tid < HID) {
        float a0 = action[0], a1 = action[1], a2 = action[2], a3 = action[3];
        s_x[tid] = ae_b[tid] + a0 * ae_w[tid * 4] + a1 * ae_w[tid * 4 + 1]
                             + a2 * ae_w[tid * 4 + 2] + a3 * ae_w[tid * 4 + 3];
        s_h[tid] = h0[tid];
    }
    __syncthreads();

    const int rows_per_blk = 4 * HID / GRID_G;  // 64
    const int r0 = blockIdx.x * rows_per_blk;
    for (int r = r0 + wid; r < r0 + rows_per_blk; r += 8) {
        const float* wi = w_ih + (size_t)r * HID;
        const float* wh = w_hh + (size_t)r * HID;
        float s = 0.f;
        #pragma unroll
        for (int k = lane; k < HID; k += 32)
            s += wi[k] * s_x[k] + wh[k] * s_h[k];
        #pragma unroll
        for (int off = 16; off; off >>= 1)
            s += __shfl_xor_sync(0xffffffffu, s, off);
        if (lane == 0) g_gates[r] = s + b_ih[r] + b_hh[r];
    }
}

// ---------------------------------------------------------------------------
// Kernel B2: softmax-partial merge + LSTM activations + logits
// out = [logits(4), h(256), c(256)]
// ---------------------------------------------------------------------------
__global__ void __launch_bounds__(256)
final_kernel(const float* __restrict__ c0, const float* __restrict__ actor_w,
             const float* __restrict__ actor_b, float* __restrict__ out)
{
    __shared__ float s_att[A];
    __shared__ float s_h[HID];
    __shared__ float s_M, s_L;
    const int tid = threadIdx.x, lane = tid & 31, wid = tid >> 5;

    if (wid == 0) {
        float m = -INFINITY;
        for (int b = lane; b < GRID_A; b += 32) m = fmaxf(m, g_m[b]);
        #pragma unroll
        for (int off = 16; off; off >>= 1)
            m = fmaxf(m, __shfl_xor_sync(0xffffffffu, m, off));
        if (lane == 0) s_M = m;
    }
    __syncthreads();
    const float M = s_M;

    if (wid == 0) {
        float l = 0.f;
        for (int b = lane; b < GRID_A; b += 32) l += g_l[b] * expf(g_m[b] - M);
        #pragma unroll
        for (int off = 16; off; off >>= 1)
            l += __shfl_xor_sync(0xffffffffu, l, off);
        if (lane == 0) s_L = l;
    }
    if (tid < A) {
        float sum = 0.f;
        for (int b = 0; b < GRID_A; ++b)
            sum += g_acc[b * A + tid] * expf(g_m[b] - M);
        s_att[tid] = sum;                     // divided by L after sync
    }
    // LSTM activations (independent of attention)
    if (tid < HID) {
        float ig = g_gates[tid];
        float fg = g_gates[HID + tid];
        float gg = g_gates[2 * HID + tid];
        float og = g_gates[3 * HID + tid];
        float si = 1.f / (1.f + expf(-ig));
        float sf = 1.f / (1.f + expf(-fg));
        float so = 1.f / (1.f + expf(-og));
        float cc = sf * c0[tid] + si * tanhf(gg);
        float hh = so * tanhf(cc);
        out[4 + tid]       = hh;
        out[4 + HID + tid] = cc;
        s_h[tid] = hh;
    }
    __syncthreads();
    if (tid < A) s_att[tid] = s_att[tid] / s_L;
    __syncthreads();

    if (wid < NA) {
        float s = 0.f;
        for (int j = lane; j < A + HID; j += 32) {
            float v = (j < A) ? s_att[j] : s_h[j - A];
            s += actor_w[wid * (A + HID) + j] * v;
        }
        #pragma unroll
        for (int off = 16; off; off >>= 1)
            s += __shfl_xor_sync(0xffffffffu, s, off);
        if (lane == 0) out[wid] = s + actor_b[wid];
    }
}

// ---------------------------------------------------------------------------
extern "C" void kernel_launch(void* const* d_in, const int* in_sizes, int n_in,
                              void* d_out, int out_size)
{
    const float* img     = (const float*)d_in[0];
    const float* action  = (const float*)d_in[1];
    const float* h0      = (const float*)d_in[2];
    const float* c0      = (const float*)d_in[3];
    const float* conv_w  = (const float*)d_in[4];
    const float* conv_b  = (const float*)d_in[5];
    const float* ae_w    = (const float*)d_in[6];
    const float* ae_b    = (const float*)d_in[7];
    const float* ia_w    = (const float*)d_in[8];
    const float* ia_b    = (const float*)d_in[9];
    // d_in[10] ha_w, d_in[11] ha_b, d_in[13] fa_b: softmax-invariant, unused
    const float* fa_w    = (const float*)d_in[12];
    const float* w_ih    = (const float*)d_in[14];
    const float* w_hh    = (const float*)d_in[15];
    const float* b_ih    = (const float*)d_in[16];
    const float* b_hh    = (const float*)d_in[17];
    const float* actor_w = (const float*)d_in[18];
    const float* actor_b = (const float*)d_in[19];
    float* out = (float*)d_out;

    const size_t smem = (size_t)SMEM_FLOATS * sizeof(float);   // ~206 KB
    cudaFuncSetAttribute(attn_kernel,
                         cudaFuncAttributeMaxDynamicSharedMemorySize, (int)smem);

    gates_kernel<<<GRID_G, 256>>>(action, h0, ae_w, ae_b, w_ih, w_hh, b_ih, b_hh);
    attn_kernel<<<GRID_A, NTHREADS, smem>>>(img, conv_w, conv_b, ia_w, ia_b, fa_w);
    final_kernel<<<1, 256>>>(c0, actor_w, actor_b, out);
}

// round 2
// speedup vs baseline: 2.4551x; 2.4551x over previous
#include <cuda_runtime.h>
#include <math.h>
#include <stdint.h>

#define C     64
#define A     128
#define HID   256
#define NA    4
#define HW    512
#define NPOS  (HW * HW)
#define TM    128
#define NTILES (NPOS / TM)       // 2048
#define GRID_A 148
#define GRID_G 128
#define NTHREADS 256

// frag-block stride: 32 lanes * 4 floats + 4 pad floats (kills STS bank conflicts)
#define FBS   132

#define IMG_F   (64 * FBS)        // 8 ksteps * 8 mtiles
#define FEAT_F  (128 * FBS)       // 16 ksteps * 8 mtiles
#define B1_F    (8 * 16 * 32 * 2)
#define B2_F    (16 * 16 * 32 * 2)
#define SMEM_FLOATS (IMG_F + FEAT_F + B1_F + B2_F + 6 * A + 8 + 4)

__device__ float g_m[GRID_A];
__device__ float g_l[GRID_A];
__device__ float g_acc[GRID_A * A];
__device__ float g_gates[4 * HID];

__device__ __forceinline__ float to_tf32(float x) {
    uint32_t u;
    asm("cvt.rna.tf32.f32 %0, %1;" : "=r"(u) : "f"(x));
    return __uint_as_float(u);
}

__device__ __forceinline__ void mma8(float* c, const float* a, const float* b) {
    asm volatile("mma.sync.aligned.m16n8k8.row.col.f32.tf32.tf32.f32 "
        "{%0,%1,%2,%3}, {%4,%5,%6,%7}, {%8,%9}, {%0,%1,%2,%3};"
        : "+f"(c[0]), "+f"(c[1]), "+f"(c[2]), "+f"(c[3])
        : "r"(__float_as_uint(a[0])), "r"(__float_as_uint(a[1])),
          "r"(__float_as_uint(a[2])), "r"(__float_as_uint(a[3])),
          "r"(__float_as_uint(b[0])), "r"(__float_as_uint(b[1])));
}

// ---------------------------------------------------------------------------
// Kernel A: tf32 tensor-core dual GEMM + online softmax, persistent 148 CTAs.
// Warp grid 4(M) x 2(N); each warp owns a 32x64 output slice of the 128x128 tile.
// ---------------------------------------------------------------------------
__global__ void __launch_bounds__(NTHREADS, 1)
attn_kernel(const float* __restrict__ img,
            const float* __restrict__ conv_w, const float* __restrict__ conv_b,
            const float* __restrict__ ia_w,   const float* __restrict__ ia_b,
            const float* __restrict__ fa_w)
{
    extern __shared__ float sm[];
    float* s_imgf  = sm;                    // frag A for GEMM1
    float* s_featf = s_imgf  + IMG_F;       // frag A for GEMM2 (tf32 feat)
    float* s_b1    = s_featf + FEAT_F;      // frag B for GEMM1 (packed once)
    float* s_b2    = s_b1    + B1_F;        // frag B for GEMM2 (packed once)
    float* s_cb    = s_b2    + B2_F;
    float* s_ib    = s_cb + A;
    float* s_fw    = s_ib + A;
    float* s_score = s_fw + A;              // [TM]
    float* s_wexp  = s_score + TM;          // [TM]
    float* s_acc   = s_wexp + TM;           // [A]
    float* s_red   = s_acc + A;             // [8]
    float* s_misc  = s_red + 8;             // m_run, l_run, new_m, scale

    const int tid    = threadIdx.x;
    const int lane   = tid & 31;
    const int wid    = tid >> 5;
    const int g      = lane >> 2;
    const int tig    = lane & 3;
    const int warp_m = wid & 3;             // 4 warps over M (32 rows each)
    const int warp_n = wid >> 2;            // 2 warps over N (64 cols each)

    // ---- one-time: pack B fragments (loop-invariant weights), tf32 ----
    // B1[k][n] = conv_w[n][k]   (conv_w is [A][C] row-major)
    for (int idx = tid; idx < B1_F; idx += NTHREADS) {
        int r = idx & 1, l = (idx >> 1) & 31, ntg = (idx >> 6) & 15, ks = idx >> 10;
        int k = ks * 8 + (l & 3) + 4 * r, n = ntg * 8 + (l >> 2);
        s_b1[idx] = to_tf32(conv_w[n * C + k]);
    }
    // B2[k][n] = ia_w[n][k]     (ia_w is [A][A] row-major)
    for (int idx = tid; idx < B2_F; idx += NTHREADS) {
        int r = idx & 1, l = (idx >> 1) & 31, ntg = (idx >> 6) & 15, ks = idx >> 10;
        int k = ks * 8 + (l & 3) + 4 * r, n = ntg * 8 + (l >> 2);
        s_b2[idx] = to_tf32(ia_w[n * A + k]);
    }
    if (tid < A) {
        s_cb[tid] = conv_b[tid];
        s_ib[tid] = ia_b[tid];
        s_fw[tid] = fa_w[tid];
        s_acc[tid] = 0.f;
    }
    if (tid == 0) { s_misc[0] = -INFINITY; s_misc[1] = 0.f; }

    float attreg[8][2];
    #pragma unroll
    for (int i = 0; i < 8; ++i) { attreg[i][0] = 0.f; attreg[i][1] = 0.f; }

    // ---- prologue prefetch of first tile ----
    float4 pf[8];
    {
        const float* src = img + (size_t)blockIdx.x * TM;
        #pragma unroll
        for (int i = 0; i < 8; ++i) {
            int idx = tid + i * NTHREADS;
            int c = idx >> 5, p4 = idx & 31;
            pf[i] = *reinterpret_cast<const float4*>(src + (size_t)c * NPOS + p4 * 4);
        }
    }
    __syncthreads();

    for (int t = blockIdx.x; t < NTILES; t += GRID_A) {
        // ---- stage img tile in fragment layout (tf32) ----
        #pragma unroll
        for (int i = 0; i < 8; ++i) {
            int idx = tid + i * NTHREADS;
            int c = idx >> 5, p4 = idx & 31;
            int ks = c >> 3, khi = (c >> 2) & 1, klo = c & 3;
            float vv[4] = {pf[i].x, pf[i].y, pf[i].z, pf[i].w};
            #pragma unroll
            for (int e = 0; e < 4; ++e) {
                int m = p4 * 4 + e;
                int fb = ks * 8 + (m >> 4);
                int dst = fb * FBS + ((m & 7) * 4 + klo) * 4 + khi * 2 + ((m >> 3) & 1);
                s_imgf[dst] = to_tf32(vv[e]);
            }
        }
        if (tid < TM) s_score[tid] = 0.f;
        __syncthreads();

        // prefetch next tile (latency hidden under both GEMMs)
        int t2 = t + GRID_A;
        if (t2 < NTILES) {
            const float* src = img + (size_t)t2 * TM;
            #pragma unroll
            for (int i = 0; i < 8; ++i) {
                int idx = tid + i * NTHREADS;
                int c = idx >> 5, p4 = idx & 31;
                pf[i] = *reinterpret_cast<const float4*>(src + (size_t)c * NPOS + p4 * 4);
            }
        }

        // ---- GEMM1: feat = img @ conv_w.T  (M=128, N=128, K=64) ----
        float acc1[2][8][4];
        #pragma unroll
        for (int mt = 0; mt < 2; ++mt)
            #pragma unroll
            for (int nt = 0; nt < 8; ++nt)
                #pragma unroll
                for (int r = 0; r < 4; ++r) acc1[mt][nt][r] = 0.f;

        #pragma unroll
        for (int ks = 0; ks < 8; ++ks) {
            float a0[2][4];
            #pragma unroll
            for (int mt = 0; mt < 2; ++mt) {
                float4 v = *reinterpret_cast<const float4*>(
                    &s_imgf[(ks * 8 + warp_m * 2 + mt) * FBS + lane * 4]);
                a0[mt][0] = v.x; a0[mt][1] = v.y; a0[mt][2] = v.z; a0[mt][3] = v.w;
            }
            #pragma unroll
            for (int nt = 0; nt < 8; ++nt) {
                float2 b = *reinterpret_cast<const float2*>(
                    &s_b1[((ks * 16 + warp_n * 8 + nt) * 32 + lane) * 2]);
                float bb[2] = {b.x, b.y};
                mma8(acc1[0][nt], a0[0], bb);
                mma8(acc1[1][nt], a0[1], bb);
            }
        }

        // ---- epilogue 1: relu+bias; keep fp32 in regs, stash tf32 frags ----
        #pragma unroll
        for (int mt = 0; mt < 2; ++mt) {
            int mtg = warp_m * 2 + mt;
            #pragma unroll
            for (int nt = 0; nt < 8; ++nt) {
                #pragma unroll
                for (int r = 0; r < 4; ++r) {
                    int cc = r & 1, rh = r >> 1;
                    int n = warp_n * 64 + nt * 8 + tig * 2 + cc;
                    float f = fmaxf(acc1[mt][nt][r] + s_cb[n], 0.f);
                    acc1[mt][nt][r] = f;                     // fp32 feat (for att acc)
                    int k = n;                               // feat col -> GEMM2 k
                    int fb = (k >> 3) * 8 + mtg;
                    int dst = fb * FBS + (g * 4 + (k & 3)) * 4 + ((k >> 2) & 1) * 2 + rh;
                    s_featf[dst] = to_tf32(f);
                }
            }
        }
        __syncthreads();

        // ---- GEMM2: att1 = feat @ ia_w.T  (M=128, N=128, K=128) ----
        float acc2[2][8][4];
        #pragma unroll
        for (int mt = 0; mt < 2; ++mt)
            #pragma unroll
            for (int nt = 0; nt < 8; ++nt)
                #pragma unroll
                for (int r = 0; r < 4; ++r) acc2[mt][nt][r] = 0.f;

        #pragma unroll
        for (int ks = 0; ks < 16; ++ks) {
            float a0[2][4];
            #pragma unroll
            for (int mt = 0; mt < 2; ++mt) {
                float4 v = *reinterpret_cast<const float4*>(
                    &s_featf[(ks * 8 + warp_m * 2 + mt) * FBS + lane * 4]);
                a0[mt][0] = v.x; a0[mt][1] = v.y; a0[mt][2] = v.z; a0[mt][3] = v.w;
            }
            #pragma unroll
            for (int nt = 0; nt < 8; ++nt) {
                float2 b = *reinterpret_cast<const float2*>(
                    &s_b2[((ks * 16 + warp_n * 8 + nt) * 32 + lane) * 2]);
                float bb[2] = {b.x, b.y};
                mma8(acc2[0][nt], a0[0], bb);
                mma8(acc2[1][nt], a0[1], bb);
            }
        }

        // ---- scores: s[p] = sum_j relu(att1 + ia_b)*fa_w ----
        #pragma unroll
        for (int mt = 0; mt < 2; ++mt) {
            #pragma unroll
            for (int rh = 0; rh < 2; ++rh) {
                float s = 0.f;
                #pragma unroll
                for (int nt = 0; nt < 8; ++nt) {
                    #pragma unroll
                    for (int cc = 0; cc < 2; ++cc) {
                        int n = warp_n * 64 + nt * 8 + tig * 2 + cc;
                        s += fmaxf(acc2[mt][nt][rh * 2 + cc] + s_ib[n], 0.f) * s_fw[n];
                    }
                }
                s += __shfl_xor_sync(0xffffffffu, s, 1);
                s += __shfl_xor_sync(0xffffffffu, s, 2);
                if (tig == 0)
                    atomicAdd(&s_score[(warp_m * 2 + mt) * 16 + g + 8 * rh], s);
            }
        }
        __syncthreads();

        // ---- online softmax bookkeeping ----
        if (tid < TM) {
            float v = s_score[tid];
            #pragma unroll
            for (int off = 16; off; off >>= 1)
                v = fmaxf(v, __shfl_xor_sync(0xffffffffu, v, off));
            if (lane == 0) s_red[wid] = v;
        }
        __syncthreads();
        if (tid == 0) {
            float mt_ = fmaxf(fmaxf(s_red[0], s_red[1]), fmaxf(s_red[2], s_red[3]));
            float m_old = s_misc[0];
            float nm = fmaxf(m_old, mt_);
            s_misc[2] = nm;
            s_misc[3] = (m_old == -INFINITY) ? 0.f : expf(m_old - nm);
        }
        __syncthreads();
        const float nm = s_misc[2], scale = s_misc[3];
        if (tid < TM) {
            float w = expf(s_score[tid] - nm);
            s_wexp[tid] = w;
            #pragma unroll
            for (int off = 16; off; off >>= 1)
                w += __shfl_xor_sync(0xffffffffu, w, off);
            if (lane == 0) s_red[wid] = w;
        }
        __syncthreads();
        if (tid == 0) {
            s_misc[1] = s_misc[1] * scale + (s_red[0] + s_red[1] + s_red[2] + s_red[3]);
            s_misc[0] = nm;
        }

        // ---- attention accumulation from fp32 feat registers ----
        float wx[2][2];
        #pragma unroll
        for (int mt = 0; mt < 2; ++mt)
            #pragma unroll
            for (int rh = 0; rh < 2; ++rh)
                wx[mt][rh] = s_wexp[(warp_m * 2 + mt) * 16 + g + 8 * rh];
        #pragma unroll
        for (int nt = 0; nt < 8; ++nt) {
            #pragma unroll
            for (int cc = 0; cc < 2; ++cc) {
                float v = wx[0][0] * acc1[0][nt][cc] + wx[0][1] * acc1[0][nt][2 + cc]
                        + wx[1][0] * acc1[1][nt][cc] + wx[1][1] * acc1[1][nt][2 + cc];
                v += __shfl_xor_sync(0xffffffffu, v, 4);
                v += __shfl_xor_sync(0xffffffffu, v, 8);
                v += __shfl_xor_sync(0xffffffffu, v, 16);
                attreg[nt][cc] = attreg[nt][cc] * scale + v;
            }
        }
        __syncthreads();   // protect s_score/s_wexp/s_misc for next tile
    }

    // ---- CTA epilogue: combine warp attregs, emit partials ----
    if (tid < A) s_acc[tid] = 0.f;
    __syncthreads();
    if (g == 0) {   // lanes 0..3 hold the g-reduced sums; tig = lane
        #pragma unroll
        for (int nt = 0; nt < 8; ++nt) {
            #pragma unroll
            for (int cc = 0; cc < 2; ++cc)
                atomicAdd(&s_acc[warp_n * 64 + nt * 8 + tig * 2 + cc], attreg[nt][cc]);
        }
    }
    __syncthreads();
    if (tid < A) g_acc[blockIdx.x * A + tid] = s_acc[tid];
    if (tid == 0) { g_m[blockIdx.x] = s_misc[0]; g_l[blockIdx.x] = s_misc[1]; }
}

// ---------------------------------------------------------------------------
// Kernel B1: LSTM gates — 128 CTAs, one row per warp, float4 loads (MLP>=4)
// ---------------------------------------------------------------------------
__global__ void __launch_bounds__(256)
gates_kernel(const float* __restrict__ action, const float* __restrict__ h0,
             const float* __restrict__ ae_w,  const float* __restrict__ ae_b,
             const float* __restrict__ w_ih,  const float* __restrict__ w_hh,
             const float* __restrict__ b_ih,  const float* __restrict__ b_hh)
{
    __shared__ float s_x[HID];
    __shared__ float s_h[HID];
    const int tid = threadIdx.x, lane = tid & 31, wid = tid >> 5;

    if (tid < HID) {
        float a0 = action[0], a1 = action[1], a2 = action[2], a3 = action[3];
        s_x[tid] = ae_b[tid] + a0 * ae_w[tid * 4] + a1 * ae_w[tid * 4 + 1]
                             + a2 * ae_w[tid * 4 + 2] + a3 * ae_w[tid * 4 + 3];
        s_h[tid] = h0[tid];
    }
    __syncthreads();

    int r = blockIdx.x * 8 + wid;                       // 1024 rows total
    const float4* wi = reinterpret_cast<const float4*>(w_ih + (size_t)r * HID);
    const float4* wh = reinterpret_cast<const float4*>(w_hh + (size_t)r * HID);
    float s = 0.f;
    #pragma unroll
    for (int j = 0; j < 2; ++j) {
        float4 u = wi[lane * 2 + j], v = wh[lane * 2 + j];
        int k = lane * 8 + j * 4;
        s += u.x * s_x[k] + u.y * s_x[k + 1] + u.z * s_x[k + 2] + u.w * s_x[k + 3];
        s += v.x * s_h[k] + v.y * s_h[k + 1] + v.z * s_h[k + 2] + v.w * s_h[k + 3];
    }
    #pragma unroll
    for (int off = 16; off; off >>= 1)
        s += __shfl_xor_sync(0xffffffffu, s, off);
    if (lane == 0) g_gates[r] = s + b_ih[r] + b_hh[r];
}

// ---------------------------------------------------------------------------
// Kernel B2: softmax-partial merge + LSTM activations + logits
// out = [logits(4), h(256), c(256)]
// ---------------------------------------------------------------------------
__global__ void __launch_bounds__(256)
final_kernel(const float* __restrict__ c0, const float* __restrict__ actor_w,
             const float* __restrict__ actor_b, float* __restrict__ out)
{
    __shared__ float s_att[A];
    __shared__ float s_h[HID];
    __shared__ float s_M, s_L;
    const int tid = threadIdx.x, lane = tid & 31, wid = tid >> 5;

    if (wid == 0) {
        float m = -INFINITY;
        for (int b = lane; b < GRID_A; b += 32) m = fmaxf(m, g_m[b]);
        #pragma unroll
        for (int off = 16; off; off >>= 1)
            m = fmaxf(m, __shfl_xor_sync(0xffffffffu, m, off));
        if (lane == 0) s_M = m;
    }
    __syncthreads();
    const float M = s_M;

    if (wid == 0) {
        float l = 0.f;
        for (int b = lane; b < GRID_A; b += 32) l += g_l[b] * expf(g_m[b] - M);
        #pragma unroll
        for (int off = 16; off; off >>= 1)
            l += __shfl_xor_sync(0xffffffffu, l, off);
        if (lane == 0) s_L = l;
    }
    if (tid < A) {
        float sum = 0.f;
        for (int b = 0; b < GRID_A; ++b)
            sum += g_acc[b * A + tid] * expf(g_m[b] - M);
        s_att[tid] = sum;
    }
    if (tid < HID) {
        float ig = g_gates[tid];
        float fg = g_gates[HID + tid];
        float gg = g_gates[2 * HID + tid];
        float og = g_gates[3 * HID + tid];
        float si = 1.f / (1.f + expf(-ig));
        float sf = 1.f / (1.f + expf(-fg));
        float so = 1.f / (1.f + expf(-og));
        float cc = sf * c0[tid] + si * tanhf(gg);
        float hh = so * tanhf(cc);
        out[4 + tid]       = hh;
        out[4 + HID + tid] = cc;
        s_h[tid] = hh;
    }
    __syncthreads();
    if (tid < A) s_att[tid] = s_att[tid] / s_L;
    __syncthreads();

    if (wid < NA) {
        float s = 0.f;
        for (int j = lane; j < A + HID; j += 32) {
            float v = (j < A) ? s_att[j] : s_h[j - A];
            s += actor_w[wid * (A + HID) + j] * v;
        }
        #pragma unroll
        for (int off = 16; off; off >>= 1)
            s += __shfl_xor_sync(0xffffffffu, s, off);
        if (lane == 0) out[wid] = s + actor_b[wid];
    }
}

// ---------------------------------------------------------------------------
extern "C" void kernel_launch(void* const* d_in, const int* in_sizes, int n_in,
                              void* d_out, int out_size)
{
    const float* img     = (const float*)d_in[0];
    const float* action  = (const float*)d_in[1];
    const float* h0      = (const float*)d_in[2];
    const float* c0      = (const float*)d_in[3];
    const float* conv_w  = (const float*)d_in[4];
    const float* conv_b  = (const float*)d_in[5];
    const float* ae_w    = (const float*)d_in[6];
    const float* ae_b    = (const float*)d_in[7];
    const float* ia_w    = (const float*)d_in[8];
    const float* ia_b    = (const float*)d_in[9];
    // d_in[10] ha_w, d_in[11] ha_b, d_in[13] fa_b: softmax-invariant, unused
    const float* fa_w    = (const float*)d_in[12];
    const float* w_ih    = (const float*)d_in[14];
    const float* w_hh    = (const float*)d_in[15];
    const float* b_ih    = (const float*)d_in[16];
    const float* b_hh    = (const float*)d_in[17];
    const float* actor_w = (const float*)d_in[18];
    const float* actor_b = (const float*)d_in[19];
    float* out = (float*)d_out;

    const size_t smem = (size_t)SMEM_FLOATS * sizeof(float);   // ~203 KB
    cudaFuncSetAttribute(attn_kernel,
                         cudaFuncAttributeMaxDynamicSharedMemorySize, (int)smem);

    gates_kernel<<<GRID_G, 256>>>(action, h0, ae_w, ae_b, w_ih, w_hh, b_ih, b_hh);
    attn_kernel<<<GRID_A, NTHREADS, smem>>>(img, conv_w, conv_b, ia_w, ia_b, fa_w);
    final_kernel<<<1, 256>>>(c0, actor_w, actor_b, out);
}

// round 4
// speedup vs baseline: 3.6484x; 1.4860x over previous
#include <cuda_runtime.h>
#include <cuda_fp16.h>
#include <math.h>
#include <stdint.h>

#define C     64
#define A     128
#define HID   256
#define NA    4
#define HW    512
#define NPOS  (HW * HW)
#define TM    128
#define NTILES (NPOS / TM)       // 2048
#define GRID_A 148
#define NTHREADS 256

// ---- dynamic SMEM byte offsets (fragment-packed fp16 operands) ----
// A-frag block (16 rows x 16 k): 32 lanes * 16B = 512B. B-frag block: 32*8B = 256B.
#define OFF_IMG   0              // 4 ks * 8 mt * 512  = 16384 B
#define OFF_FEAT  16384          // 8 ks * 8 mt * 512  = 32768 B
#define OFF_B1    49152          // 4 ks * 16 nt * 256 = 16384 B
#define OFF_B2    65536          // 8 ks * 16 nt * 256 = 32768 B
#define OFF_TAIL  98304
// tail float indices (relative to float* sm)
#define TF_BASE   (OFF_TAIL / 4)
#define TI_MISC   (TF_BASE + 0)      // 4: m_run, l_run, new_m, scale
#define TI_RED    (TF_BASE + 4)      // 8
#define TI_CB     (TF_BASE + 16)     // 128
#define TI_IB     (TF_BASE + 144)    // 128
#define TI_FW     (TF_BASE + 272)    // 128
#define TI_SCORE  (TF_BASE + 400)    // 128
#define TI_WEXP   (TF_BASE + 528)    // 128
#define TI_ACC    (TF_BASE + 656)    // 128
#define TI_SX     (TF_BASE + 784)    // 256
#define TI_SH     (TF_BASE + 1040)   // 256
#define SMEM_BYTES (OFF_TAIL + 1296 * 4)

__device__ float g_m[GRID_A];
__device__ float g_l[GRID_A];
__device__ float g_acc[GRID_A * A];
__device__ float g_gates[4 * HID];

__device__ __forceinline__ void mma16(float* c, const uint32_t* a, const uint32_t* b) {
    asm volatile("mma.sync.aligned.m16n8k16.row.col.f32.f16.f16.f32 "
        "{%0,%1,%2,%3}, {%4,%5,%6,%7}, {%8,%9}, {%0,%1,%2,%3};"
        : "+f"(c[0]), "+f"(c[1]), "+f"(c[2]), "+f"(c[3])
        : "r"(a[0]), "r"(a[1]), "r"(a[2]), "r"(a[3]), "r"(b[0]), "r"(b[1]));
}

__device__ __forceinline__ uint32_t h2(float lo, float hi) {
    __half2 v = __floats2half2_rn(lo, hi);
    return *reinterpret_cast<uint32_t*>(&v);
}

// ---------------------------------------------------------------------------
// Kernel A: fp16 m16n8k16 dual GEMM + online softmax. Persistent 148 CTAs.
// Warp grid 4(M) x 2(N). Blocks 0..127 also compute LSTM gate rows.
// ---------------------------------------------------------------------------
__global__ void __launch_bounds__(NTHREADS, 1)
attn_kernel(const float* __restrict__ img,
            const float* __restrict__ conv_w, const float* __restrict__ conv_b,
            const float* __restrict__ ia_w,   const float* __restrict__ ia_b,
            const float* __restrict__ fa_w,
            const float* __restrict__ action, const float* __restrict__ h0,
            const float* __restrict__ ae_w,   const float* __restrict__ ae_b,
            const float* __restrict__ w_ih,   const float* __restrict__ w_hh,
            const float* __restrict__ b_ih,   const float* __restrict__ b_hh)
{
    extern __shared__ __align__(1024) float sm[];
    char* smc = (char*)sm;

    const int tid    = threadIdx.x;
    const int lane   = tid & 31;
    const int wid    = tid >> 5;
    const int g      = lane >> 2;          // fragment group (row within 8)
    const int tig    = lane & 3;           // thread-in-group (col pair)
    const int warp_m = wid & 3;            // 4 warps over M (32 rows each)
    const int warp_n = wid >> 2;           // 2 warps over N (64 cols each)

    // ---- one-time: pack B1 (conv_w [128n x 64k]) fragments, fp16 ----
    for (int idx = tid; idx < 4 * 16 * 32 * 2; idx += NTHREADS) {
        int r = idx & 1, l = (idx >> 1) & 31, nt = (idx >> 6) & 15, ks = idx >> 10;
        int n = nt * 8 + (l >> 2);
        int k0 = ks * 16 + (l & 3) * 2 + r * 8;
        *(uint32_t*)(smc + OFF_B1 + (ks * 16 + nt) * 256 + l * 8 + r * 4) =
            h2(conv_w[n * C + k0], conv_w[n * C + k0 + 1]);
    }
    // ---- pack B2 (ia_w [128n x 128k]) ----
    for (int idx = tid; idx < 8 * 16 * 32 * 2; idx += NTHREADS) {
        int r = idx & 1, l = (idx >> 1) & 31, nt = (idx >> 6) & 15, ks = idx >> 10;
        int n = nt * 8 + (l >> 2);
        int k0 = ks * 16 + (l & 3) * 2 + r * 8;
        *(uint32_t*)(smc + OFF_B2 + (ks * 16 + nt) * 256 + l * 8 + r * 4) =
            h2(ia_w[n * A + k0], ia_w[n * A + k0 + 1]);
    }
    if (tid < A) {
        sm[TI_CB + tid] = conv_b[tid];
        sm[TI_IB + tid] = ia_b[tid];
        sm[TI_FW + tid] = fa_w[tid];
        sm[TI_ACC + tid] = 0.f;
    }
    if (tid == 0) { sm[TI_MISC + 0] = -INFINITY; sm[TI_MISC + 1] = 0.f; }
    if (blockIdx.x < 128) {     // gates: x = ae(action) + ae_b, stash h0
        float a0 = action[0], a1 = action[1], a2 = action[2], a3 = action[3];
        sm[TI_SX + tid] = ae_b[tid] + a0 * ae_w[tid * 4] + a1 * ae_w[tid * 4 + 1]
                                    + a2 * ae_w[tid * 4 + 2] + a3 * ae_w[tid * 4 + 3];
        sm[TI_SH + tid] = h0[tid];
    }
    __syncthreads();

    // ---- folded LSTM gates: one row per warp for blocks < 128 ----
    if (blockIdx.x < 128) {
        int r = blockIdx.x * 8 + wid;
        const float4* wi = (const float4*)(w_ih + (size_t)r * HID);
        const float4* wh = (const float4*)(w_hh + (size_t)r * HID);
        float s = 0.f;
        #pragma unroll
        for (int j = 0; j < 2; ++j) {
            float4 u = wi[lane * 2 + j], v = wh[lane * 2 + j];
            int k = lane * 8 + j * 4;
            s += u.x * sm[TI_SX + k] + u.y * sm[TI_SX + k + 1]
               + u.z * sm[TI_SX + k + 2] + u.w * sm[TI_SX + k + 3];
            s += v.x * sm[TI_SH + k] + v.y * sm[TI_SH + k + 1]
               + v.z * sm[TI_SH + k + 2] + v.w * sm[TI_SH + k + 3];
        }
        #pragma unroll
        for (int off = 16; off; off >>= 1) s += __shfl_xor_sync(0xffffffffu, s, off);
        if (lane == 0) g_gates[r] = s + b_ih[r] + b_hh[r];
    }

    // staging mapping: thread owns position sp, channels sch*32..+31
    const int sp  = tid & 127, sch = tid >> 7;
    const int smt = sp >> 4, sg = sp & 7, srh = (sp >> 3) & 1;

    float attreg[8][2];
    #pragma unroll
    for (int i = 0; i < 8; ++i) { attreg[i][0] = 0.f; attreg[i][1] = 0.f; }

    // prologue prefetch (tile blockIdx.x)
    float rimg[32];
    {
        const float* srcb = img + (size_t)(sch * 32) * NPOS + (size_t)blockIdx.x * TM + sp;
        #pragma unroll
        for (int k = 0; k < 32; ++k) rimg[k] = srcb[(size_t)k * NPOS];
    }

    for (int t = blockIdx.x; t < NTILES; t += GRID_A) {
        // ---- stage img tile into fp16 A fragments ----
        #pragma unroll
        for (int j = 0; j < 16; ++j) {
            int ks  = sch * 2 + (j >> 3);
            int tg  = j & 3;
            int hb  = (j >> 2) & 1;
            int reg = srh + 2 * hb;
            *(uint32_t*)(smc + OFF_IMG + (ks * 8 + smt) * 512 + (sg * 4 + tg) * 16 + reg * 4) =
                h2(rimg[2 * j], rimg[2 * j + 1]);
        }
        if (tid < TM) sm[TI_SCORE + tid] = 0.f;
        __syncthreads();

        // prefetch next tile (hidden under both GEMMs)
        int t2 = t + GRID_A;
        if (t2 < NTILES) {
            const float* srcb = img + (size_t)(sch * 32) * NPOS + (size_t)t2 * TM + sp;
            #pragma unroll
            for (int k = 0; k < 32; ++k) rimg[k] = srcb[(size_t)k * NPOS];
        }

        // ---- GEMM1: feat = img @ conv_w^T  (M=128,N=128,K=64; 4 k16-steps) ----
        float acc1[2][8][4];
        #pragma unroll
        for (int mt = 0; mt < 2; ++mt)
            #pragma unroll
            for (int nt = 0; nt < 8; ++nt)
                #pragma unroll
                for (int r = 0; r < 4; ++r) acc1[mt][nt][r] = 0.f;

        #pragma unroll
        for (int ks = 0; ks < 4; ++ks) {
            uint32_t a[2][4];
            #pragma unroll
            for (int mt = 0; mt < 2; ++mt) {
                uint4 v = *(const uint4*)(smc + OFF_IMG +
                    (ks * 8 + warp_m * 2 + mt) * 512 + lane * 16);
                a[mt][0] = v.x; a[mt][1] = v.y; a[mt][2] = v.z; a[mt][3] = v.w;
            }
            #pragma unroll
            for (int nt = 0; nt < 8; ++nt) {
                uint2 b = *(const uint2*)(smc + OFF_B1 +
                    (ks * 16 + warp_n * 8 + nt) * 256 + lane * 8);
                uint32_t bb[2] = {b.x, b.y};
                mma16(acc1[0][nt], a[0], bb);
                mma16(acc1[1][nt], a[1], bb);
            }
        }

        // ---- epilogue 1: bias+relu (keep fp32 for att acc); write fp16 A2 frags ----
        // D(g,tig) fragment of feat == A(g,tig) fragment for GEMM2: own-lane identity.
        #pragma unroll
        for (int mt = 0; mt < 2; ++mt) {
            #pragma unroll
            for (int nt = 0; nt < 8; ++nt) {
                float b0 = sm[TI_CB + warp_n * 64 + nt * 8 + tig * 2];
                float b1 = sm[TI_CB + warp_n * 64 + nt * 8 + tig * 2 + 1];
                acc1[mt][nt][0] = fmaxf(acc1[mt][nt][0] + b0, 0.f);
                acc1[mt][nt][1] = fmaxf(acc1[mt][nt][1] + b1, 0.f);
                acc1[mt][nt][2] = fmaxf(acc1[mt][nt][2] + b0, 0.f);
                acc1[mt][nt][3] = fmaxf(acc1[mt][nt][3] + b1, 0.f);
            }
            #pragma unroll
            for (int k2 = 0; k2 < 4; ++k2) {   // ks2 = warp_n*4 + k2
                uint4 v;
                v.x = h2(acc1[mt][k2 * 2][0],     acc1[mt][k2 * 2][1]);      // rh0 hb0
                v.y = h2(acc1[mt][k2 * 2][2],     acc1[mt][k2 * 2][3]);      // rh1 hb0
                v.z = h2(acc1[mt][k2 * 2 + 1][0], acc1[mt][k2 * 2 + 1][1]);  // rh0 hb1
                v.w = h2(acc1[mt][k2 * 2 + 1][2], acc1[mt][k2 * 2 + 1][3]);  // rh1 hb1
                *(uint4*)(smc + OFF_FEAT +
                    ((warp_n * 4 + k2) * 8 + warp_m * 2 + mt) * 512 + lane * 16) = v;
            }
        }
        __syncthreads();

        // ---- GEMM2: att1 = feat @ ia_w^T  (K=128; 8 k16-steps) ----
        float acc2[2][8][4];
        #pragma unroll
        for (int mt = 0; mt < 2; ++mt)
            #pragma unroll
            for (int nt = 0; nt < 8; ++nt)
                #pragma unroll
                for (int r = 0; r < 4; ++r) acc2[mt][nt][r] = 0.f;

        #pragma unroll
        for (int ks = 0; ks < 8; ++ks) {
            uint32_t a[2][4];
            #pragma unroll
            for (int mt = 0; mt < 2; ++mt) {
                uint4 v = *(const uint4*)(smc + OFF_FEAT +
                    (ks * 8 + warp_m * 2 + mt) * 512 + lane * 16);
                a[mt][0] = v.x; a[mt][1] = v.y; a[mt][2] = v.z; a[mt][3] = v.w;
            }
            #pragma unroll
            for (int nt = 0; nt < 8; ++nt) {
                uint2 b = *(const uint2*)(smc + OFF_B2 +
                    (ks * 16 + warp_n * 8 + nt) * 256 + lane * 8);
                uint32_t bb[2] = {b.x, b.y};
                mma16(acc2[0][nt], a[0], bb);
                mma16(acc2[1][nt], a[1], bb);
            }
        }

        // ---- scores: s[p] = sum_j relu(att1 + ia_b) * fa_w ----
        #pragma unroll
        for (int mt = 0; mt < 2; ++mt) {
            #pragma unroll
            for (int rh = 0; rh < 2; ++rh) {
                float s = 0.f;
                #pragma unroll
                for (int nt = 0; nt < 8; ++nt) {
                    #pragma unroll
                    for (int cc = 0; cc < 2; ++cc) {
                        int n = warp_n * 64 + nt * 8 + tig * 2 + cc;
                        s += fmaxf(acc2[mt][nt][rh * 2 + cc] + sm[TI_IB + n], 0.f) * sm[TI_FW + n];
                    }
                }
                s += __shfl_xor_sync(0xffffffffu, s, 1);
                s += __shfl_xor_sync(0xffffffffu, s, 2);
                if (tig == 0)
                    atomicAdd(&sm[TI_SCORE + (warp_m * 2 + mt) * 16 + g + 8 * rh], s);
            }
        }
        __syncthreads();

        // ---- online softmax bookkeeping ----
        if (tid < TM) {
            float v = sm[TI_SCORE + tid];
            #pragma unroll
            for (int off = 16; off; off >>= 1)
                v = fmaxf(v, __shfl_xor_sync(0xffffffffu, v, off));
            if (lane == 0) sm[TI_RED + wid] = v;
        }
        __syncthreads();
        if (tid == 0) {
            float mt_ = fmaxf(fmaxf(sm[TI_RED], sm[TI_RED + 1]),
                              fmaxf(sm[TI_RED + 2], sm[TI_RED + 3]));
            float m_old = sm[TI_MISC];
            float nm = fmaxf(m_old, mt_);
            sm[TI_MISC + 2] = nm;
            sm[TI_MISC + 3] = (m_old == -INFINITY) ? 0.f : expf(m_old - nm);
        }
        __syncthreads();
        const float nm = sm[TI_MISC + 2], scale = sm[TI_MISC + 3];
        if (tid < TM) {
            float w = expf(sm[TI_SCORE + tid] - nm);
            sm[TI_WEXP + tid] = w;
            #pragma unroll
            for (int off = 16; off; off >>= 1)
                w += __shfl_xor_sync(0xffffffffu, w, off);
            if (lane == 0) sm[TI_RED + wid] = w;
        }
        __syncthreads();
        if (tid == 0) {
            sm[TI_MISC + 1] = sm[TI_MISC + 1] * scale
                            + (sm[TI_RED] + sm[TI_RED + 1] + sm[TI_RED + 2] + sm[TI_RED + 3]);
            sm[TI_MISC] = nm;
        }

        // ---- attention accumulation from fp32 feat registers ----
        float wx[2][2];
        #pragma unroll
        for (int mt = 0; mt < 2; ++mt)
            #pragma unroll
            for (int rh = 0; rh < 2; ++rh)
                wx[mt][rh] = sm[TI_WEXP + (warp_m * 2 + mt) * 16 + g + 8 * rh];
        #pragma unroll
        for (int nt = 0; nt < 8; ++nt) {
            #pragma unroll
            for (int cc = 0; cc < 2; ++cc) {
                float v = wx[0][0] * acc1[0][nt][cc] + wx[0][1] * acc1[0][nt][2 + cc]
                        + wx[1][0] * acc1[1][nt][cc] + wx[1][1] * acc1[1][nt][2 + cc];
                v += __shfl_xor_sync(0xffffffffu, v, 4);
                v += __shfl_xor_sync(0xffffffffu, v, 8);
                v += __shfl_xor_sync(0xffffffffu, v, 16);
                attreg[nt][cc] = attreg[nt][cc] * scale + v;
            }
        }
        __syncthreads();
    }

    // ---- CTA epilogue: combine warp attregs, emit partials ----
    if (g == 0) {   // lanes 0..3 hold the g-reduced sums; tig = lane
        #pragma unroll
        for (int nt = 0; nt < 8; ++nt) {
            #pragma unroll
            for (int cc = 0; cc < 2; ++cc)
                atomicAdd(&sm[TI_ACC + warp_n * 64 + nt * 8 + tig * 2 + cc], attreg[nt][cc]);
        }
    }
    __syncthreads();
    if (tid < A) g_acc[blockIdx.x * A + tid] = sm[TI_ACC + tid];
    if (tid == 0) { g_m[blockIdx.x] = sm[TI_MISC]; g_l[blockIdx.x] = sm[TI_MISC + 1]; }
}

// ---------------------------------------------------------------------------
// Kernel B: softmax-partial merge + LSTM activations + logits
// out = [logits(4), h(256), c(256)]
// ---------------------------------------------------------------------------
__global__ void __launch_bounds__(256)
final_kernel(const float* __restrict__ c0, const float* __restrict__ actor_w,
             const float* __restrict__ actor_b, float* __restrict__ out)
{
    __shared__ float s_att[A];
    __shared__ float s_h[HID];
    __shared__ float s_M, s_L;
    const int tid = threadIdx.x, lane = tid & 31, wid = tid >> 5;

    if (wid == 0) {
        float m = -INFINITY;
        for (int b = lane; b < GRID_A; b += 32) m = fmaxf(m, g_m[b]);
        #pragma unroll
        for (int off = 16; off; off >>= 1)
            m = fmaxf(m, __shfl_xor_sync(0xffffffffu, m, off));
        if (lane == 0) s_M = m;
    }
    __syncthreads();
    const float M = s_M;

    if (wid == 0) {
        float l = 0.f;
        for (int b = lane; b < GRID_A; b += 32) l += g_l[b] * expf(g_m[b] - M);
        #pragma unroll
        for (int off = 16; off; off >>= 1)
            l += __shfl_xor_sync(0xffffffffu, l, off);
        if (lane == 0) s_L = l;
    }
    if (tid < A) {
        float sum = 0.f;
        for (int b = 0; b < GRID_A; ++b)
            sum += g_acc[b * A + tid] * expf(g_m[b] - M);
        s_att[tid] = sum;
    }
    if (tid < HID) {
        float ig = g_gates[tid];
        float fg = g_gates[HID + tid];
        float gg = g_gates[2 * HID + tid];
        float og = g_gates[3 * HID + tid];
        float si = 1.f / (1.f + expf(-ig));
        float sf = 1.f / (1.f + expf(-fg));
        float so = 1.f / (1.f + expf(-og));
        float cc = sf * c0[tid] + si * tanhf(gg);
        float hh = so * tanhf(cc);
        out[4 + tid]       = hh;
        out[4 + HID + tid] = cc;
        s_h[tid] = hh;
    }
    __syncthreads();
    if (tid < A) s_att[tid] = s_att[tid] / s_L;
    __syncthreads();

    if (wid < NA) {
        float s = 0.f;
        for (int j = lane; j < A + HID; j += 32) {
            float v = (j < A) ? s_att[j] : s_h[j - A];
            s += actor_w[wid * (A + HID) + j] * v;
        }
        #pragma unroll
        for (int off = 16; off; off >>= 1)
            s += __shfl_xor_sync(0xffffffffu, s, off);
        if (lane == 0) out[wid] = s + actor_b[wid];
    }
}

// ---------------------------------------------------------------------------
extern "C" void kernel_launch(void* const* d_in, const int* in_sizes, int n_in,
                              void* d_out, int out_size)
{
    const float* img     = (const float*)d_in[0];
    const float* action  = (const float*)d_in[1];
    const float* h0      = (const float*)d_in[2];
    const float* c0      = (const float*)d_in[3];
    const float* conv_w  = (const float*)d_in[4];
    const float* conv_b  = (const float*)d_in[5];
    const float* ae_w    = (const float*)d_in[6];
    const float* ae_b    = (const float*)d_in[7];
    const float* ia_w    = (const float*)d_in[8];
    const float* ia_b    = (const float*)d_in[9];
    // d_in[10] ha_w, d_in[11] ha_b, d_in[13] fa_b: softmax-invariant, unused
    const float* fa_w    = (const float*)d_in[12];
    const float* w_ih    = (const float*)d_in[14];
    const float* w_hh    = (const float*)d_in[15];
    const float* b_ih    = (const float*)d_in[16];
    const float* b_hh    = (const float*)d_in[17];
    const float* actor_w = (const float*)d_in[18];
    const float* actor_b = (const float*)d_in[19];
    float* out = (float*)d_out;

    cudaFuncSetAttribute(attn_kernel,
                         cudaFuncAttributeMaxDynamicSharedMemorySize, SMEM_BYTES);

    attn_kernel<<<GRID_A, NTHREADS, SMEM_BYTES>>>(img, conv_w, conv_b, ia_w, ia_b, fa_w,
                                                  action, h0, ae_w, ae_b,
                                                  w_ih, w_hh, b_ih, b_hh);
    final_kernel<<<1, 256>>>(c0, actor_w, actor_b, out);
}

// round 5
// speedup vs baseline: 4.1311x; 1.1323x over previous
#include <cuda_runtime.h>
#include <cuda_fp16.h>
#include <math.h>
#include <stdint.h>

#define C     64
#define A     128
#define HID   256
#define NA    4
#define HW    512
#define NPOS  (HW * HW)
#define TM    128
#define NTILES (NPOS / TM)       // 2048
#define GRID_A 148
#define NTHREADS 256

// ---- dynamic SMEM byte offsets (fragment-packed fp16 operands) ----
#define OFF_IMG   0              // 4 ks * 8 mt * 512  = 16384 B
#define OFF_FEAT  16384          // 8 ks * 8 mt * 512  = 32768 B
#define OFF_B1    49152          // 4 ks * 16 nt * 256 = 16384 B
#define OFF_B2    65536          // 8 ks * 16 nt * 256 = 32768 B
#define OFF_TAIL  98304
#define TF_BASE   (OFF_TAIL / 4)
#define TI_RED    (TF_BASE + 0)      // 8
#define TI_CB     (TF_BASE + 16)     // 128
#define TI_IB     (TF_BASE + 144)    // 128
#define TI_FW     (TF_BASE + 272)    // 128
#define TI_SCORE  (TF_BASE + 400)    // 128 (reused as merge half-1)
#define TI_WEXP   (TF_BASE + 528)    // 128
#define TI_ACC    (TF_BASE + 656)    // 128 (reused as merge att)
#define TI_SX     (TF_BASE + 784)    // 256 (reused as merge h)
#define TI_SH     (TF_BASE + 1040)   // 256
#define SMEM_BYTES (OFF_TAIL + 1296 * 4)

__device__ float g_l[GRID_A];
__device__ float g_acc[GRID_A * A];
__device__ float g_gates[4 * HID];
__device__ unsigned int g_cnt;       // zero-init; last CTA resets after merge

__device__ __forceinline__ void mma16(float* c, const uint32_t* a, const uint32_t* b) {
    asm volatile("mma.sync.aligned.m16n8k16.row.col.f32.f16.f16.f32 "
        "{%0,%1,%2,%3}, {%4,%5,%6,%7}, {%8,%9}, {%0,%1,%2,%3};"
        : "+f"(c[0]), "+f"(c[1]), "+f"(c[2]), "+f"(c[3])
        : "r"(a[0]), "r"(a[1]), "r"(a[2]), "r"(a[3]), "r"(b[0]), "r"(b[1]));
}

__device__ __forceinline__ uint32_t h2(float lo, float hi) {
    __half2 v = __floats2half2_rn(lo, hi);
    return *reinterpret_cast<uint32_t*>(&v);
}

// ---------------------------------------------------------------------------
// Persistent fused kernel: fp16 dual GEMM + softmax-weighted pooling;
// blocks 0..127 also compute LSTM gate rows; last CTA to finish does the
// global merge + LSTM activations + logits.
// ---------------------------------------------------------------------------
__global__ void __launch_bounds__(NTHREADS, 1)
attn_kernel(const float* __restrict__ img,
            const float* __restrict__ conv_w, const float* __restrict__ conv_b,
            const float* __restrict__ ia_w,   const float* __restrict__ ia_b,
            const float* __restrict__ fa_w,
            const float* __restrict__ action, const float* __restrict__ h0,
            const float* __restrict__ ae_w,   const float* __restrict__ ae_b,
            const float* __restrict__ w_ih,   const float* __restrict__ w_hh,
            const float* __restrict__ b_ih,   const float* __restrict__ b_hh,
            const float* __restrict__ c0,     const float* __restrict__ actor_w,
            const float* __restrict__ actor_b, float* __restrict__ out)
{
    extern __shared__ __align__(1024) float sm[];
    char* smc = (char*)sm;
    __shared__ unsigned int s_isLast;

    const int tid    = threadIdx.x;
    const int lane   = tid & 31;
    const int wid    = tid >> 5;
    const int g      = lane >> 2;
    const int tig    = lane & 3;
    const int warp_m = wid & 3;
    const int warp_n = wid >> 2;

    // ---- one-time: pack B1 (conv_w [128n x 64k]) fragments, fp16 ----
    for (int idx = tid; idx < 4 * 16 * 32 * 2; idx += NTHREADS) {
        int r = idx & 1, l = (idx >> 1) & 31, nt = (idx >> 6) & 15, ks = idx >> 10;
        int n = nt * 8 + (l >> 2);
        int k0 = ks * 16 + (l & 3) * 2 + r * 8;
        *(uint32_t*)(smc + OFF_B1 + (ks * 16 + nt) * 256 + l * 8 + r * 4) =
            h2(conv_w[n * C + k0], conv_w[n * C + k0 + 1]);
    }
    // ---- pack B2 (ia_w [128n x 128k]) ----
    for (int idx = tid; idx < 8 * 16 * 32 * 2; idx += NTHREADS) {
        int r = idx & 1, l = (idx >> 1) & 31, nt = (idx >> 6) & 15, ks = idx >> 10;
        int n = nt * 8 + (l >> 2);
        int k0 = ks * 16 + (l & 3) * 2 + r * 8;
        *(uint32_t*)(smc + OFF_B2 + (ks * 16 + nt) * 256 + l * 8 + r * 4) =
            h2(ia_w[n * A + k0], ia_w[n * A + k0 + 1]);
    }
    if (tid < A) {
        sm[TI_CB + tid] = conv_b[tid];
        sm[TI_IB + tid] = ia_b[tid];
        sm[TI_FW + tid] = fa_w[tid];
        sm[TI_ACC + tid] = 0.f;
    }
    if (blockIdx.x < 128) {     // gates: x = ae(action) + ae_b, stash h0
        float a0 = action[0], a1 = action[1], a2 = action[2], a3 = action[3];
        sm[TI_SX + tid] = ae_b[tid] + a0 * ae_w[tid * 4] + a1 * ae_w[tid * 4 + 1]
                                    + a2 * ae_w[tid * 4 + 2] + a3 * ae_w[tid * 4 + 3];
        sm[TI_SH + tid] = h0[tid];
    }
    __syncthreads();

    // ---- folded LSTM gates: one row per warp for blocks < 128 ----
    if (blockIdx.x < 128) {
        int r = blockIdx.x * 8 + wid;
        const float4* wi = (const float4*)(w_ih + (size_t)r * HID);
        const float4* wh = (const float4*)(w_hh + (size_t)r * HID);
        float s = 0.f;
        #pragma unroll
        for (int j = 0; j < 2; ++j) {
            float4 u = wi[lane * 2 + j], v = wh[lane * 2 + j];
            int k = lane * 8 + j * 4;
            s += u.x * sm[TI_SX + k] + u.y * sm[TI_SX + k + 1]
               + u.z * sm[TI_SX + k + 2] + u.w * sm[TI_SX + k + 3];
            s += v.x * sm[TI_SH + k] + v.y * sm[TI_SH + k + 1]
               + v.z * sm[TI_SH + k + 2] + v.w * sm[TI_SH + k + 3];
        }
        #pragma unroll
        for (int off = 16; off; off >>= 1) s += __shfl_xor_sync(0xffffffffu, s, off);
        if (lane == 0) g_gates[r] = s + b_ih[r] + b_hh[r];
    }

    // staging mapping: thread owns position sp, channels sch*32..+31
    const int sp  = tid & 127, sch = tid >> 7;
    const int smt = sp >> 4, sg = sp & 7, srh = (sp >> 3) & 1;

    float attreg[8][2];
    #pragma unroll
    for (int i = 0; i < 8; ++i) { attreg[i][0] = 0.f; attreg[i][1] = 0.f; }
    float l_run = 0.f;   // only tid==0's copy is used

    // prologue prefetch (tile blockIdx.x)
    float rimg[32];
    {
        const float* srcb = img + (size_t)(sch * 32) * NPOS + (size_t)blockIdx.x * TM + sp;
        #pragma unroll
        for (int k = 0; k < 32; ++k) rimg[k] = srcb[(size_t)k * NPOS];
    }

    for (int t = blockIdx.x; t < NTILES; t += GRID_A) {
        // ---- stage img tile into fp16 A fragments ----
        #pragma unroll
        for (int j = 0; j < 16; ++j) {
            int ks  = sch * 2 + (j >> 3);
            int tg  = j & 3;
            int hb  = (j >> 2) & 1;
            int reg = srh + 2 * hb;
            *(uint32_t*)(smc + OFF_IMG + (ks * 8 + smt) * 512 + (sg * 4 + tg) * 16 + reg * 4) =
                h2(rimg[2 * j], rimg[2 * j + 1]);
        }
        if (tid < TM) sm[TI_SCORE + tid] = 0.f;
        __syncthreads();                                   // sync 1

        // prefetch next tile (hidden under both GEMMs)
        int t2 = t + GRID_A;
        if (t2 < NTILES) {
            const float* srcb = img + (size_t)(sch * 32) * NPOS + (size_t)t2 * TM + sp;
            #pragma unroll
            for (int k = 0; k < 32; ++k) rimg[k] = srcb[(size_t)k * NPOS];
        }

        // ---- GEMM1: feat = img @ conv_w^T  (K=64; 4 k16-steps) ----
        float acc1[2][8][4];
        #pragma unroll
        for (int mt = 0; mt < 2; ++mt)
            #pragma unroll
            for (int nt = 0; nt < 8; ++nt)
                #pragma unroll
                for (int r = 0; r < 4; ++r) acc1[mt][nt][r] = 0.f;

        #pragma unroll
        for (int ks = 0; ks < 4; ++ks) {
            uint32_t a[2][4];
            #pragma unroll
            for (int mt = 0; mt < 2; ++mt) {
                uint4 v = *(const uint4*)(smc + OFF_IMG +
                    (ks * 8 + warp_m * 2 + mt) * 512 + lane * 16);
                a[mt][0] = v.x; a[mt][1] = v.y; a[mt][2] = v.z; a[mt][3] = v.w;
            }
            #pragma unroll
            for (int nt = 0; nt < 8; ++nt) {
                uint2 b = *(const uint2*)(smc + OFF_B1 +
                    (ks * 16 + warp_n * 8 + nt) * 256 + lane * 8);
                uint32_t bb[2] = {b.x, b.y};
                mma16(acc1[0][nt], a[0], bb);
                mma16(acc1[1][nt], a[1], bb);
            }
        }

        // ---- epilogue 1: bias+relu; own-lane identity repack to fp16 A2 ----
        #pragma unroll
        for (int mt = 0; mt < 2; ++mt) {
            #pragma unroll
            for (int nt = 0; nt < 8; ++nt) {
                float b0 = sm[TI_CB + warp_n * 64 + nt * 8 + tig * 2];
                float b1 = sm[TI_CB + warp_n * 64 + nt * 8 + tig * 2 + 1];
                acc1[mt][nt][0] = fmaxf(acc1[mt][nt][0] + b0, 0.f);
                acc1[mt][nt][1] = fmaxf(acc1[mt][nt][1] + b1, 0.f);
                acc1[mt][nt][2] = fmaxf(acc1[mt][nt][2] + b0, 0.f);
                acc1[mt][nt][3] = fmaxf(acc1[mt][nt][3] + b1, 0.f);
            }
            #pragma unroll
            for (int k2 = 0; k2 < 4; ++k2) {
                uint4 v;
                v.x = h2(acc1[mt][k2 * 2][0],     acc1[mt][k2 * 2][1]);
                v.y = h2(acc1[mt][k2 * 2][2],     acc1[mt][k2 * 2][3]);
                v.z = h2(acc1[mt][k2 * 2 + 1][0], acc1[mt][k2 * 2 + 1][1]);
                v.w = h2(acc1[mt][k2 * 2 + 1][2], acc1[mt][k2 * 2 + 1][3]);
                *(uint4*)(smc + OFF_FEAT +
                    ((warp_n * 4 + k2) * 8 + warp_m * 2 + mt) * 512 + lane * 16) = v;
            }
        }
        __syncthreads();                                   // sync 2

        // ---- GEMM2: att1 = feat @ ia_w^T  (K=128; 8 k16-steps) ----
        float acc2[2][8][4];
        #pragma unroll
        for (int mt = 0; mt < 2; ++mt)
            #pragma unroll
            for (int nt = 0; nt < 8; ++nt)
                #pragma unroll
                for (int r = 0; r < 4; ++r) acc2[mt][nt][r] = 0.f;

        #pragma unroll
        for (int ks = 0; ks < 8; ++ks) {
            uint32_t a[2][4];
            #pragma unroll
            for (int mt = 0; mt < 2; ++mt) {
                uint4 v = *(const uint4*)(smc + OFF_FEAT +
                    (ks * 8 + warp_m * 2 + mt) * 512 + lane * 16);
                a[mt][0] = v.x; a[mt][1] = v.y; a[mt][2] = v.z; a[mt][3] = v.w;
            }
            #pragma unroll
            for (int nt = 0; nt < 8; ++nt) {
                uint2 b = *(const uint2*)(smc + OFF_B2 +
                    (ks * 16 + warp_n * 8 + nt) * 256 + lane * 8);
                uint32_t bb[2] = {b.x, b.y};
                mma16(acc2[0][nt], a[0], bb);
                mma16(acc2[1][nt], a[1], bb);
            }
        }

        // ---- scores: s[p] = sum_j relu(att1 + ia_b) * fa_w ----
        #pragma unroll
        for (int mt = 0; mt < 2; ++mt) {
            #pragma unroll
            for (int rh = 0; rh < 2; ++rh) {
                float s = 0.f;
                #pragma unroll
                for (int nt = 0; nt < 8; ++nt) {
                    #pragma unroll
                    for (int cc = 0; cc < 2; ++cc) {
                        int n = warp_n * 64 + nt * 8 + tig * 2 + cc;
                        s += fmaxf(acc2[mt][nt][rh * 2 + cc] + sm[TI_IB + n], 0.f) * sm[TI_FW + n];
                    }
                }
                s += __shfl_xor_sync(0xffffffffu, s, 1);
                s += __shfl_xor_sync(0xffffffffu, s, 2);
                if (tig == 0)
                    atomicAdd(&sm[TI_SCORE + (warp_m * 2 + mt) * 16 + g + 8 * rh], s);
            }
        }
        __syncthreads();                                   // sync 3

        // ---- max-free softmax weights (scores bounded far below exp overflow) ----
        if (tid < TM) {
            float w = expf(sm[TI_SCORE + tid]);
            sm[TI_WEXP + tid] = w;
            #pragma unroll
            for (int off = 16; off; off >>= 1)
                w += __shfl_xor_sync(0xffffffffu, w, off);
            if (lane == 0) sm[TI_RED + wid] = w;
        }
        __syncthreads();                                   // sync 4
        if (tid == 0)
            l_run += sm[TI_RED] + sm[TI_RED + 1] + sm[TI_RED + 2] + sm[TI_RED + 3];

        // ---- attention accumulation from fp32 feat registers ----
        float wx[2][2];
        #pragma unroll
        for (int mt = 0; mt < 2; ++mt)
            #pragma unroll
            for (int rh = 0; rh < 2; ++rh)
                wx[mt][rh] = sm[TI_WEXP + (warp_m * 2 + mt) * 16 + g + 8 * rh];
        #pragma unroll
        for (int nt = 0; nt < 8; ++nt) {
            #pragma unroll
            for (int cc = 0; cc < 2; ++cc) {
                float v = wx[0][0] * acc1[0][nt][cc] + wx[0][1] * acc1[0][nt][2 + cc]
                        + wx[1][0] * acc1[1][nt][cc] + wx[1][1] * acc1[1][nt][2 + cc];
                v += __shfl_xor_sync(0xffffffffu, v, 4);
                v += __shfl_xor_sync(0xffffffffu, v, 8);
                v += __shfl_xor_sync(0xffffffffu, v, 16);
                attreg[nt][cc] += v;
            }
        }
        // no trailing sync needed: next-tile writers to s_score/s_wexp are
        // ordered behind sync 3/4, which readers here have already passed.
    }

    // ---- CTA epilogue: combine warp attregs, emit partials ----
    __syncthreads();
    if (g == 0) {   // lanes 0..3 hold the g-reduced sums; tig = lane
        #pragma unroll
        for (int nt = 0; nt < 8; ++nt) {
            #pragma unroll
            for (int cc = 0; cc < 2; ++cc)
                atomicAdd(&sm[TI_ACC + warp_n * 64 + nt * 8 + tig * 2 + cc], attreg[nt][cc]);
        }
    }
    __syncthreads();
    if (tid < A) g_acc[blockIdx.x * A + tid] = sm[TI_ACC + tid];
    if (tid == 0) g_l[blockIdx.x] = l_run;

    // ---- last-CTA merge: softmax normalize + LSTM + logits ----
    __threadfence();
    __syncthreads();
    if (tid == 0) s_isLast = (atomicAdd(&g_cnt, 1u) == GRID_A - 1);
    __syncthreads();
    if (!s_isLast) return;
    __threadfence();

    // L = sum g_l
    if (wid == 0) {
        float l = 0.f;
        for (int b = lane; b < GRID_A; b += 32) l += g_l[b];
        #pragma unroll
        for (int off = 16; off; off >>= 1)
            l += __shfl_xor_sync(0xffffffffu, l, off);
        if (lane == 0) sm[TI_RED] = l;
    }
    // half-column partial sums of g_acc (2 threads per column, MLP-rich)
    {
        int a = tid & 127, hh = tid >> 7;
        const float* src = g_acc + (size_t)(hh * 74) * A + a;
        float p = 0.f;
        #pragma unroll 4
        for (int b = 0; b < 74; ++b) p += src[(size_t)b * A];
        sm[(hh ? TI_SCORE : TI_ACC) + a] = p;
    }
    // LSTM activations from g_gates
    {
        float ig = g_gates[tid];
        float fg = g_gates[HID + tid];
        float gg = g_gates[2 * HID + tid];
        float og = g_gates[3 * HID + tid];
        float si = 1.f / (1.f + expf(-ig));
        float sf = 1.f / (1.f + expf(-fg));
        float so = 1.f / (1.f + expf(-og));
        float cc = sf * c0[tid] + si * tanhf(gg);
        float hh = so * tanhf(cc);
        out[4 + tid]       = hh;
        out[4 + HID + tid] = cc;
        sm[TI_SX + tid] = hh;
    }
    __syncthreads();
    if (tid < A)
        sm[TI_ACC + tid] = (sm[TI_ACC + tid] + sm[TI_SCORE + tid]) / sm[TI_RED];
    __syncthreads();

    if (wid < NA) {
        float s = 0.f;
        for (int j = lane; j < A + HID; j += 32) {
            float v = (j < A) ? sm[TI_ACC + j] : sm[TI_SX + j - A];
            s += actor_w[wid * (A + HID) + j] * v;
        }
        #pragma unroll
        for (int off = 16; off; off >>= 1)
            s += __shfl_xor_sync(0xffffffffu, s, off);
        if (lane == 0) out[wid] = s + actor_b[wid];
    }
    if (tid == 0) g_cnt = 0;   // reset for next graph replay
}

// ---------------------------------------------------------------------------
extern "C" void kernel_launch(void* const* d_in, const int* in_sizes, int n_in,
                              void* d_out, int out_size)
{
    const float* img     = (const float*)d_in[0];
    const float* action  = (const float*)d_in[1];
    const float* h0      = (const float*)d_in[2];
    const float* c0      = (const float*)d_in[3];
    const float* conv_w  = (const float*)d_in[4];
    const float* conv_b  = (const float*)d_in[5];
    const float* ae_w    = (const float*)d_in[6];
    const float* ae_b    = (const float*)d_in[7];
    const float* ia_w    = (const float*)d_in[8];
    const float* ia_b    = (const float*)d_in[9];
    // d_in[10] ha_w, d_in[11] ha_b, d_in[13] fa_b: softmax-invariant, unused
    const float* fa_w    = (const float*)d_in[12];
    const float* w_ih    = (const float*)d_in[14];
    const float* w_hh    = (const float*)d_in[15];
    const float* b_ih    = (const float*)d_in[16];
    const float* b_hh    = (const float*)d_in[17];
    const float* actor_w = (const float*)d_in[18];
    const float* actor_b = (const float*)d_in[19];
    float* out = (float*)d_out;

    cudaFuncSetAttribute(attn_kernel,
                         cudaFuncAttributeMaxDynamicSharedMemorySize, SMEM_BYTES);

    attn_kernel<<<GRID_A, NTHREADS, SMEM_BYTES>>>(img, conv_w, conv_b, ia_w, ia_b, fa_w,
                                                  action, h0, ae_w, ae_b,
                                                  w_ih, w_hh, b_ih, b_hh,
                                                  c0, actor_w, actor_b, out);
}